// round 3
// baseline (speedup 1.0000x reference)
#include <cuda_runtime.h>

#define BATCH   32
#define SEQ_LEN 4096
#define D_K     128
#define HALF    64                 // D_K / 2 rotation frequencies
#define ROW4    (D_K / 4)          // float4 per row = 32
#define THREADS 256
#define POS_PER_BLOCK 2
#define ITERS   (BATCH * ROW4 / THREADS)   // 4 float4 per thread per position

__global__ __launch_bounds__(THREADS) void rope_fused2_kernel(
    const float* __restrict__ x,
    const int*   __restrict__ token_positions,
    float*       __restrict__ out)
{
    // cs[0..63]  = {cos,sin} for position p0
    // cs[64..127]= {cos,sin} for position p1
    __shared__ float2 cs[POS_PER_BLOCK * HALF];

    const int t  = threadIdx.x;
    const int p0 = blockIdx.x * POS_PER_BLOCK;      // two adjacent positions

    const int q          = t & 31;                  // float4 column within row
    const int b0         = t >> 5;                  // first batch slab
    const int rowStride4 = SEQ_LEN * ROW4;          // 131072 float4 per batch slab
    const int baseA      = p0 * ROW4 + q;           // p1 row is +ROW4

    const float4* __restrict__ x4 = (const float4*)x;
    float4*       __restrict__ o4 = (float4*)out;

    // ---- front-batch ALL 8 global loads (MLP_p1 = 8) ----
    float4 v[2 * ITERS];
    #pragma unroll
    for (int i = 0; i < ITERS; i++) {
        const int idx = (b0 + 8 * i) * rowStride4 + baseA;
        v[2 * i]     = x4[idx];            // position p0
        v[2 * i + 1] = x4[idx + ROW4];     // position p1 (adjacent 512B row)
    }

    // ---- threads 0..127: one sincos each (64 freqs x 2 positions) ----
    if (t < POS_PER_BLOCK * HALF) {
        const int j = t & (HALF - 1);
        const int p = p0 + (t >> 6);

        // L = log2(10000)/64 split hi/lo; double-float exact j*L
        const double Ld   = 0.20762050593046014;
        const float  L_hi = (float)Ld;
        const float  L_lo = (float)(Ld - (double)L_hi);

        const float jf   = (float)j;
        const float ehi  = jf * L_hi;
        const float eerr = fmaf(jf, L_hi, -ehi);
        const float elo  = eerr + jf * L_lo;

        float inv = exp2f(-ehi);
        inv = inv - inv * (0.6931471805599453f * elo);

        const float ang = (float)token_positions[p] * inv;
        float s, c;
        sincosf(ang, &s, &c);
        cs[t] = make_float2(c, s);
    }
    __syncthreads();

    // One float4 smem read per position: {cos2q, sin2q, cos2q+1, sin2q+1}
    const float4 cwA = ((const float4*)cs)[q];
    const float4 cwB = ((const float4*)cs)[32 + q];

    #pragma unroll
    for (int i = 0; i < ITERS; i++) {
        const int idx = (b0 + 8 * i) * rowStride4 + baseA;

        float4 a = v[2 * i];
        float4 r;
        r.x = a.x * cwA.x - a.y * cwA.y;
        r.y = a.x * cwA.y + a.y * cwA.x;
        r.z = a.z * cwA.z - a.w * cwA.w;
        r.w = a.z * cwA.w + a.w * cwA.z;
        o4[idx] = r;

        float4 b = v[2 * i + 1];
        float4 s;
        s.x = b.x * cwB.x - b.y * cwB.y;
        s.y = b.x * cwB.y + b.y * cwB.x;
        s.z = b.z * cwB.z - b.w * cwB.w;
        s.w = b.z * cwB.w + b.w * cwB.z;
        o4[idx + ROW4] = s;
    }
}

extern "C" void kernel_launch(void* const* d_in, const int* in_sizes, int n_in,
                              void* d_out, int out_size) {
    const float* x   = (const float*)d_in[0];
    const int*   pos = (const int*)d_in[1];
    float*       out = (float*)d_out;

    rope_fused2_kernel<<<SEQ_LEN / POS_PER_BLOCK, THREADS>>>(x, pos, out);
}

// round 4
// speedup vs baseline: 1.1357x; 1.1357x over previous
#include <cuda_runtime.h>

#define BATCH   32
#define SEQ_LEN 4096
#define D_K     128
#define HALF    64                 // D_K / 2 rotation frequencies
#define ROW4    (D_K / 4)          // float4 per row = 32
#define THREADS 256
#define POS_PER_BLOCK 2
#define ITERS   (BATCH * ROW4 / THREADS)   // 4 float4 per thread per position

__global__ __launch_bounds__(THREADS) void rope_fused3_kernel(
    const float* __restrict__ x,
    const int*   __restrict__ token_positions,
    float*       __restrict__ out)
{
    // cs[0..63]  = {cos,sin} for position p0
    // cs[64..127]= {cos,sin} for position p1
    __shared__ float2 cs[POS_PER_BLOCK * HALF];

    const int t  = threadIdx.x;
    const int p0 = blockIdx.x * POS_PER_BLOCK;      // two adjacent positions

    const int q          = t & 31;                  // float4 column within row
    const int b0         = t >> 5;                  // first batch slab
    const int rowStride4 = SEQ_LEN * ROW4;          // 131072 float4 per batch slab
    const int baseA      = p0 * ROW4 + q;           // p1 row is +ROW4

    const float4* __restrict__ x4 = (const float4*)x;
    float4*       __restrict__ o4 = (float4*)out;

    // ---- front-batch all 8 global loads (DEFAULT policy: x should stay in L2) ----
    float4 v[2 * ITERS];
    #pragma unroll
    for (int i = 0; i < ITERS; i++) {
        const int idx = (b0 + 8 * i) * rowStride4 + baseA;
        v[2 * i]     = x4[idx];            // position p0
        v[2 * i + 1] = x4[idx + ROW4];     // position p1 (adjacent 512B row)
    }

    // ---- threads 0..127: one sincos each (64 freqs x 2 positions) ----
    if (t < POS_PER_BLOCK * HALF) {
        const int j = t & (HALF - 1);
        const int p = p0 + (t >> 6);

        // L = log2(10000)/64 split hi/lo; double-float exact j*L
        const double Ld   = 0.20762050593046014;
        const float  L_hi = (float)Ld;
        const float  L_lo = (float)(Ld - (double)L_hi);

        const float jf   = (float)j;
        const float ehi  = jf * L_hi;
        const float eerr = fmaf(jf, L_hi, -ehi);
        const float elo  = eerr + jf * L_lo;

        float inv = exp2f(-ehi);
        inv = inv - inv * (0.6931471805599453f * elo);

        const float ang = (float)token_positions[p] * inv;
        float s, c;
        sincosf(ang, &s, &c);
        cs[t] = make_float2(c, s);
    }
    __syncthreads();

    // One float4 smem read per position: {cos2q, sin2q, cos2q+1, sin2q+1}
    const float4 cwA = ((const float4*)cs)[q];
    const float4 cwB = ((const float4*)cs)[32 + q];

    #pragma unroll
    for (int i = 0; i < ITERS; i++) {
        const int idx = (b0 + 8 * i) * rowStride4 + baseA;

        float4 a = v[2 * i];
        float4 r;
        r.x = a.x * cwA.x - a.y * cwA.y;
        r.y = a.x * cwA.y + a.y * cwA.x;
        r.z = a.z * cwA.z - a.w * cwA.w;
        r.w = a.z * cwA.w + a.w * cwA.z;
        __stcs(&o4[idx], r);               // evict-first: don't displace x in L2

        float4 b = v[2 * i + 1];
        float4 s;
        s.x = b.x * cwB.x - b.y * cwB.y;
        s.y = b.x * cwB.y + b.y * cwB.x;
        s.z = b.z * cwB.z - b.w * cwB.w;
        s.w = b.z * cwB.w + b.w * cwB.z;
        __stcs(&o4[idx + ROW4], s);        // evict-first
    }
}

extern "C" void kernel_launch(void* const* d_in, const int* in_sizes, int n_in,
                              void* d_out, int out_size) {
    const float* x   = (const float*)d_in[0];
    const int*   pos = (const int*)d_in[1];
    float*       out = (float*)d_out;

    rope_fused3_kernel<<<SEQ_LEN / POS_PER_BLOCK, THREADS>>>(x, pos, out);
}